// round 16
// baseline (speedup 1.0000x reference)
#include <cuda_runtime.h>
#include <cuda_fp16.h>
#include <math_constants.h>
#include <cstdint>

#define NB    4
#define SQ    2048
#define UU    1024
#define DKD   64
#define NEGC  1.0e9f
#define SCL   0.125f   // 1/sqrt(64)
#define NSPL  2        // key splits

// ---------------- scratch (no allocation allowed) ----------------
// g_Qh / g_Kh: [8192][64] fp16, d-dim PAIR-PERMUTED per 16-group:
//   pos 4j..4j+3 hold d = {2j, 2j+1, 2j+8, 2j+9}
// g_Vth: [B][64(d)][2048(s)] fp16, transposed, s pair-permuted per 16-group
// g_Wph: [3][64][1024] fp16 pair-permuted weights (proj B operand)
__device__ __half g_Qh[(size_t)NB * SQ * DKD];
__device__ __half g_Kh[(size_t)NB * SQ * DKD];
__device__ __half g_Vth[(size_t)NB * DKD * SQ];
__device__ __half g_Wph[(size_t)3 * DKD * UU];
// split-K partials
__device__ float g_Po[(size_t)NSPL * NB * SQ * DKD];
__device__ float g_Pm[(size_t)NSPL * NB * SQ];
__device__ float g_Pl[(size_t)NSPL * NB * SQ];

// ---------------- helpers ----------------
__device__ __forceinline__ uint32_t packh2(float lo, float hi) {
    __half2 h = __floats2half2_rn(lo, hi);   // .x (low) = lo
    return reinterpret_cast<uint32_t&>(h);
}
// fp16 m16n8k16, f32 accum
__device__ __forceinline__ void mma16h(float* c,
                                       uint32_t a0, uint32_t a1, uint32_t a2, uint32_t a3,
                                       uint32_t b0, uint32_t b1) {
    asm volatile(
        "mma.sync.aligned.m16n8k16.row.col.f32.f16.f16.f32 "
        "{%0,%1,%2,%3}, {%4,%5,%6,%7}, {%8,%9}, {%0,%1,%2,%3};\n"
        : "+f"(c[0]), "+f"(c[1]), "+f"(c[2]), "+f"(c[3])
        : "r"(a0), "r"(a1), "r"(a2), "r"(a3), "r"(b0), "r"(b1));
}
__device__ __forceinline__ uint32_t smem_u32(const void* p) {
    uint32_t a;
    asm("{ .reg .u64 t; cvta.to.shared.u64 t, %1; cvt.u32.u64 %0, t; }" : "=r"(a) : "l"(p));
    return a;
}
#define CP16(dst, src) \
    asm volatile("cp.async.cg.shared.global [%0], [%1], 16;\n" :: "r"(dst), "l"(src))
#define CPCOMMIT() asm volatile("cp.async.commit_group;\n" ::: "memory")
#define CPWAIT(n)  asm volatile("cp.async.wait_group %0;\n" :: "n"(n) : "memory")

// =======================================================================
// W prep: fp16-round + pair-permute all three weight matrices into g_Wph.
// Each thread handles 8 consecutive k of one row (one aligned half-group).
// =======================================================================
__global__ __launch_bounds__(256) void wprep(
    const float* __restrict__ Wq, const float* __restrict__ Wk, const float* __restrict__ Wv)
{
    int gid = blockIdx.x * 256 + threadIdx.x;   // 0..24575
    int which = gid >> 13;
    int rem = gid & 8191;
    const float* W = (which == 0) ? Wq : (which == 1) ? Wk : Wv;
    const float* src = W + (size_t)rem * 8;
    float4 lo = *(const float4*)(src);
    float4 hi = *(const float4*)(src + 4);
    int row = rem >> 7;            // 1024/8 = 128 groups per row
    int k0  = (rem & 127) * 8;
    // pair (k,k+1) at r=k%16 -> pos-in-group = 4*((r&7)>>1) + 2*(r>>3)
    __half* dsth = g_Wph + (size_t)which * (DKD * UU) + (size_t)row * 1024
                 + (k0 & ~15) + ((k0 & 8) ? 2 : 0);
    *(uint32_t*)(dsth + 0)  = packh2(lo.x, lo.y);
    *(uint32_t*)(dsth + 4)  = packh2(lo.z, lo.w);
    *(uint32_t*)(dsth + 8)  = packh2(hi.x, hi.y);
    *(uint32_t*)(dsth + 12) = packh2(hi.z, hi.w);
}

// =======================================================================
// Projection GEMM, fp16 m16n8k16: cp.async 3-stage, k-steps of 32.
// CTA: 64 rows x 64 cols, 128 threads (4 warps x 16 rows). grid (128, 3).
// X staged raw fp32 (pitch 36 floats); A packed to f16x2 post-LDS.
// W staged fp16 pre-permuted (pitch 72 halves = 36 words, conflict-free).
// Stage = 9216B X + 9216B W = 18432B; 3 stages = 55296B -> 3 CTAs/SM.
// =======================================================================
#define PSTB   18432
#define PWOFFB 9216
#define PSTAGES 3
#define PROJ_SMEM_BYTES (PSTAGES * PSTB)        // 55296

__global__ __launch_bounds__(128, 3) void proj_tc(
    const float* __restrict__ Qx, const float* __restrict__ bq,
    const float* __restrict__ Kx, const float* __restrict__ bk,
    const float* __restrict__ Vx, const float* __restrict__ bv)
{
    extern __shared__ char smraw[];
    float* sm = (float*)smraw;
    const uint32_t sb = smem_u32(smraw);

    const int which = blockIdx.y;
    const float* X    = (which == 0) ? Qx : (which == 1) ? Kx : Vx;
    const float* bias = (which == 0) ? bq : (which == 1) ? bk : bv;
    const __half* Wp  = g_Wph + (size_t)which * (DKD * UU);

    const int tid = threadIdx.x;
    const int w   = tid >> 5;
    const int lane = tid & 31;
    const int g = lane >> 2;
    const int t = lane & 3;
    const int m0 = blockIdx.x * 64;

    auto issue = [&](int s) {
        const int k0 = s * 32;
        const uint32_t bs = sb + (uint32_t)((s % PSTAGES) * PSTB);
        // X: 64 rows x 128B (32 floats), 512 cp16
        #pragma unroll
        for (int i = 0; i < 4; i++) {
            int idx = tid + i * 128;
            int r = idx >> 3, seg = idx & 7;
            CP16(bs + (uint32_t)(r * 144 + seg * 16),
                 X + (size_t)(m0 + r) * UU + k0 + seg * 4);
        }
        // W: 64 rows x 64B (32 halves), 256 cp16
        #pragma unroll
        for (int i = 0; i < 2; i++) {
            int idx = tid + i * 128;
            int r = idx >> 2, seg = idx & 3;
            CP16(bs + (uint32_t)(PWOFFB + r * 144 + seg * 16),
                 Wp + (size_t)r * UU + k0 + seg * 8);
        }
        CPCOMMIT();
    };

    issue(0); issue(1);

    float acc[8][4] = {};

    for (int kc = 0; kc < 32; kc++) {
        if (kc + 2 < 32) { issue(kc + 2); CPWAIT(2); }
        else             { CPWAIT(0); }
        __syncthreads();

        const float*  bX  = (const float*)(smraw + (kc % PSTAGES) * PSTB);
        const __half* bWh = (const __half*)(smraw + (kc % PSTAGES) * PSTB + PWOFFB);
        const float* xr0 = &bX[(w * 16 + g) * 36];
        const float* xr1 = &bX[(w * 16 + 8 + g) * 36];

        #pragma unroll
        for (int ks = 0; ks < 2; ks++) {
            const int cb = ks * 16;
            float2 xl0 = *(const float2*)(xr0 + cb + 2 * t);
            float2 xh0 = *(const float2*)(xr0 + cb + 2 * t + 8);
            float2 xl1 = *(const float2*)(xr1 + cb + 2 * t);
            float2 xh1 = *(const float2*)(xr1 + cb + 2 * t + 8);
            uint32_t a0 = packh2(xl0.x, xl0.y);
            uint32_t a1 = packh2(xl1.x, xl1.y);
            uint32_t a2 = packh2(xh0.x, xh0.y);
            uint32_t a3 = packh2(xh1.x, xh1.y);
            #pragma unroll
            for (int nb = 0; nb < 8; nb++) {
                uint2 b = *(const uint2*)&bWh[(nb * 8 + g) * 72 + cb + 4 * t];
                mma16h(acc[nb], a0, a1, a2, a3, b.x, b.y);
            }
        }
        __syncthreads();
    }

    // epilogue (identical to round 15)
    const int lr0 = w * 16 + g, lr1 = lr0 + 8;
    const int t2 = 2 * t;

    if (which < 2) {
        __half* dst = (which == 0) ? g_Qh : g_Kh;
        #pragma unroll
        for (int nb = 0; nb < 8; nb++) {
            float b0 = bias[nb * 8 + t2], b1 = bias[nb * 8 + t2 + 1];
            int pos = 16 * (nb >> 1) + 2 * (nb & 1) + 4 * t;
            uint32_t h0 = packh2(acc[nb][0] + b0, acc[nb][1] + b1);
            uint32_t h1 = packh2(acc[nb][2] + b0, acc[nb][3] + b1);
            *(uint32_t*)(dst + (size_t)(m0 + lr0) * 64 + pos) = h0;
            *(uint32_t*)(dst + (size_t)(m0 + lr1) * 64 + pos) = h1;
        }
    } else {
        float* ob = sm;   // [64][68], fits in stage region
        #pragma unroll
        for (int nb = 0; nb < 8; nb++) {
            float b0 = bias[nb * 8 + t2], b1 = bias[nb * 8 + t2 + 1];
            ob[lr0 * 68 + nb * 8 + t2]     = acc[nb][0] + b0;
            ob[lr0 * 68 + nb * 8 + t2 + 1] = acc[nb][1] + b1;
            ob[lr1 * 68 + nb * 8 + t2]     = acc[nb][2] + b0;
            ob[lr1 * 68 + nb * 8 + t2 + 1] = acc[nb][3] + b1;
        }
        __syncthreads();
        const int bidx = m0 >> 11;
        const int sbase = m0 & 2047;
        #pragma unroll
        for (int i = 0; i < 8; i++) {
            int idx = tid + i * 128;       // 64 d * 16 s-groups of 4
            int d = idx >> 4, mg = idx & 15;
            float v0 = ob[(mg * 4 + 0) * 68 + d];
            float v1 = ob[(mg * 4 + 1) * 68 + d];
            float v2 = ob[(mg * 4 + 2) * 68 + d];
            float v3 = ob[(mg * 4 + 3) * 68 + d];
            int a = mg & 3;
            int grp = (sbase >> 4) + (mg >> 2);
            int p0 = (a & 1) * 8 + (a >> 1) * 2;
            __half* vrow = g_Vth + ((size_t)(bidx * 64 + d)) * 2048 + grp * 16;
            *(uint32_t*)(vrow + p0)     = packh2(v0, v1);
            *(uint32_t*)(vrow + p0 + 4) = packh2(v2, v3);
        }
    }
}

// =======================================================================
// Flash attention (round-15 proven): split-K, fp16 m16n8k16.
// CTA = 4 warps x 16 full query rows, 1024 keys/split, 8 tiles of 128.
// grid (32, 2, 4) = 256 CTAs, 2 CTAs/SM. smem 49152 B.
// =======================================================================
#define H_QS   0
#define H_KS   (64 * 80)                  // 5120
#define H_VT   (H_KS + 128 * 80)          // 15360
#define ATT_SMEM_BYTES ((H_VT + 64 * 144) * 2)   // 49152

__global__ __launch_bounds__(128, 2) void attn_tc(
    const int* __restrict__ mask)
{
    extern __shared__ __half smh[];
    const int tid = threadIdx.x;
    const int w = tid >> 5;
    const int lane = tid & 31;
    const int g = lane >> 2;
    const int t = lane & 3;
    const int qt = blockIdx.x;
    const int sp = blockIdx.y;
    const int bb = blockIdx.z;
    const int q0 = qt * 64;
    const int kbase = sp * (SQ / NSPL);

    // stage Q tile (fp16 permuted, straight copy: 64 rows x 128B)
    const __half* Qg = g_Qh + ((size_t)(bb * SQ + q0)) * 64;
    #pragma unroll
    for (int i = 0; i < 4; i++) {
        int idx = tid + i * 128;
        int r = idx >> 3, seg = idx & 7;
        *(float4*)((char*)smh + r * 160 + seg * 16) =
            *(const float4*)(Qg + (size_t)r * 64 + seg * 8);
    }
    __syncthreads();

    uint2 qa0[4], qa1[4];
    {
        const __half* r0p = smh + H_QS + (w * 16 + g) * 80 + 4 * t;
        const __half* r1p = smh + H_QS + (w * 16 + 8 + g) * 80 + 4 * t;
        #pragma unroll
        for (int ks = 0; ks < 4; ks++) {
            qa0[ks] = *(const uint2*)(r0p + ks * 16);
            qa1[ks] = *(const uint2*)(r1p + ks * 16);
        }
    }

    float m0r = -CUDART_INF_F, m1r = -CUDART_INF_F;
    float l0r = 0.f, l1r = 0.f;
    float o[8][4] = {};

    const int row0 = q0 + w * 16 + g, row1 = row0 + 8;
    const int* mk0 = mask + ((size_t)(bb * SQ + row0)) * SQ + kbase;
    const int* mk1 = mask + ((size_t)(bb * SQ + row1)) * SQ + kbase;
    const __half* Kg = g_Kh + ((size_t)(bb * SQ + kbase)) * 64;
    const __half* Vg = g_Vth + ((size_t)bb * 64) * 2048 + kbase;

    for (int tile = 0; tile < (SQ / NSPL) / 128; tile++) {
        const int j0 = tile * 128;

        __syncthreads();
        #pragma unroll
        for (int i = 0; i < 8; i++) {
            int idx = tid + i * 128;
            int r = idx >> 3, seg = idx & 7;
            *(float4*)((char*)smh + H_KS * 2 + r * 160 + seg * 16) =
                *(const float4*)(Kg + (size_t)(j0 + r) * 64 + seg * 8);
        }
        #pragma unroll
        for (int i = 0; i < 8; i++) {
            int idx = tid + i * 128;
            int d = idx >> 4, seg = idx & 15;
            *(float4*)((char*)smh + H_VT * 2 + d * 288 + seg * 16) =
                *(const float4*)(Vg + (size_t)d * 2048 + j0 + seg * 8);
        }
        __syncthreads();

        // ---- MMA1: scores 16q x 128j ----
        float sa[16][4];
        #pragma unroll
        for (int nb = 0; nb < 16; nb++) {
            sa[nb][0] = 0.f; sa[nb][1] = 0.f; sa[nb][2] = 0.f; sa[nb][3] = 0.f;
            const __half* kr = smh + H_KS + (nb * 8 + g) * 80 + 4 * t;
            #pragma unroll
            for (int ks = 0; ks < 4; ks++) {
                uint2 b = *(const uint2*)(kr + ks * 16);
                mma16h(sa[nb], qa0[ks].x, qa1[ks].x, qa0[ks].y, qa1[ks].y, b.x, b.y);
            }
        }

        // ---- mask + scale ----
        #pragma unroll
        for (int nb = 0; nb < 16; nb++) {
            int2 mv0 = *(const int2*)(mk0 + j0 + nb * 8 + 2 * t);
            int2 mv1 = *(const int2*)(mk1 + j0 + nb * 8 + 2 * t);
            sa[nb][0] = mv0.x ? sa[nb][0] * SCL : -NEGC;
            sa[nb][1] = mv0.y ? sa[nb][1] * SCL : -NEGC;
            sa[nb][2] = mv1.x ? sa[nb][2] * SCL : -NEGC;
            sa[nb][3] = mv1.y ? sa[nb][3] * SCL : -NEGC;
        }

        // ---- row max (quad reduce) ----
        float mx0 = -CUDART_INF_F, mx1 = -CUDART_INF_F;
        #pragma unroll
        for (int nb = 0; nb < 16; nb++) {
            mx0 = fmaxf(mx0, fmaxf(sa[nb][0], sa[nb][1]));
            mx1 = fmaxf(mx1, fmaxf(sa[nb][2], sa[nb][3]));
        }
        mx0 = fmaxf(mx0, __shfl_xor_sync(0xffffffffu, mx0, 1));
        mx0 = fmaxf(mx0, __shfl_xor_sync(0xffffffffu, mx0, 2));
        mx1 = fmaxf(mx1, __shfl_xor_sync(0xffffffffu, mx1, 1));
        mx1 = fmaxf(mx1, __shfl_xor_sync(0xffffffffu, mx1, 2));

        float nm0 = fmaxf(m0r, mx0), nm1 = fmaxf(m1r, mx1);
        float c0 = __expf(m0r - nm0), c1 = __expf(m1r - nm1);
        m0r = nm0; m1r = nm1;

        // ---- exp + sums; pack P to fp16x2 ----
        uint32_t pt[16][2];
        float s0 = 0.f, s1 = 0.f;
        #pragma unroll
        for (int nb = 0; nb < 16; nb++) {
            float p0 = __expf(sa[nb][0] - nm0);
            float p1 = __expf(sa[nb][1] - nm0);
            float p2 = __expf(sa[nb][2] - nm1);
            float p3 = __expf(sa[nb][3] - nm1);
            s0 += p0 + p1; s1 += p2 + p3;
            pt[nb][0] = packh2(p0, p1);
            pt[nb][1] = packh2(p2, p3);
        }
        s0 += __shfl_xor_sync(0xffffffffu, s0, 1);
        s0 += __shfl_xor_sync(0xffffffffu, s0, 2);
        s1 += __shfl_xor_sync(0xffffffffu, s1, 1);
        s1 += __shfl_xor_sync(0xffffffffu, s1, 2);
        l0r = l0r * c0 + s0;
        l1r = l1r * c1 + s1;

        #pragma unroll
        for (int nd = 0; nd < 8; nd++) {
            o[nd][0] *= c0; o[nd][1] *= c0;
            o[nd][2] *= c1; o[nd][3] *= c1;
        }

        // ---- MMA2: O += P . V ----
        #pragma unroll
        for (int nd = 0; nd < 8; nd++) {
            const __half* vr = smh + H_VT + (nd * 8 + g) * 144 + 4 * t;
            #pragma unroll
            for (int ks = 0; ks < 8; ks++) {
                uint2 b = *(const uint2*)(vr + ks * 16);
                mma16h(o[nd],
                       pt[2 * ks][0], pt[2 * ks][1],
                       pt[2 * ks + 1][0], pt[2 * ks + 1][1],
                       b.x, b.y);
            }
        }
    }

    // ---- write split partials ----
    const size_t sr0 = (size_t)sp * (NB * SQ) + (size_t)bb * SQ + row0;
    const size_t sr1 = sr0 + 8;
    #pragma unroll
    for (int nd = 0; nd < 8; nd++) {
        *(float2*)(g_Po + sr0 * 64 + nd * 8 + 2 * t) = make_float2(o[nd][0], o[nd][1]);
        *(float2*)(g_Po + sr1 * 64 + nd * 8 + 2 * t) = make_float2(o[nd][2], o[nd][3]);
    }
    if (t == 0) {
        g_Pm[sr0] = m0r; g_Pl[sr0] = l0r;
        g_Pm[sr1] = m1r; g_Pl[sr1] = l1r;
    }
}

// =======================================================================
// split combine (round-12 proven version)
// =======================================================================
__global__ __launch_bounds__(256) void combine_k(float* __restrict__ out)
{
    int gid = blockIdx.x * 256 + threadIdx.x;
    int row = gid >> 4;
    int c4 = gid & 15;
    float m1 = g_Pm[row], m2 = g_Pm[NB * SQ + row];
    float l1 = g_Pl[row], l2 = g_Pl[NB * SQ + row];
    float m = fmaxf(m1, m2);
    float w1 = __expf(m1 - m), w2 = __expf(m2 - m);
    float inv = 1.0f / (w1 * l1 + w2 * l2);
    w1 *= inv; w2 *= inv;
    float4 o1 = *(const float4*)(g_Po + (size_t)row * 64 + c4 * 4);
    float4 o2 = *(const float4*)(g_Po + ((size_t)(NB * SQ + row)) * 64 + c4 * 4);
    float4 r;
    r.x = o1.x * w1 + o2.x * w2;
    r.y = o1.y * w1 + o2.y * w2;
    r.z = o1.z * w1 + o2.z * w2;
    r.w = o1.w * w1 + o2.w * w2;
    *(float4*)(out + (size_t)row * 64 + c4 * 4) = r;
}

// ---------------- launch ----------------
extern "C" void kernel_launch(void* const* d_in, const int* in_sizes, int n_in,
                              void* d_out, int out_size)
{
    const float* Q    = (const float*)d_in[0];
    const float* K    = (const float*)d_in[1];
    const float* V    = (const float*)d_in[2];
    const int*   mask = (const int*)  d_in[3];
    const float* Wq   = (const float*)d_in[4];
    const float* bq   = (const float*)d_in[5];
    const float* Wk   = (const float*)d_in[6];
    const float* bk   = (const float*)d_in[7];
    const float* Wv   = (const float*)d_in[8];
    const float* bv   = (const float*)d_in[9];
    float* out = (float*)d_out;

    (void)in_sizes; (void)n_in; (void)out_size;

    const int proj_smem = PROJ_SMEM_BYTES;   // 55296
    const int att_smem  = ATT_SMEM_BYTES;    // 49152
    cudaFuncSetAttribute(proj_tc, cudaFuncAttributeMaxDynamicSharedMemorySize, proj_smem);
    cudaFuncSetAttribute(attn_tc, cudaFuncAttributeMaxDynamicSharedMemorySize, att_smem);

    wprep<<<96, 256>>>(Wq, Wk, Wv);
    proj_tc<<<dim3(128, 3), 128, proj_smem>>>(Q, bq, K, bk, V, bv);
    attn_tc<<<dim3(32, NSPL, NB), 128, att_smem>>>(mask);
    combine_k<<<(NB * SQ * 16) / 256, 256>>>(out);
}